// round 2
// baseline (speedup 1.0000x reference)
#include <cuda_runtime.h>
#include <math.h>

#define BB   32
#define TT_  2048
#define CIN  80
#define HCH  256
#define MT   128           // t-tile per CTA
#define NT   32            // h-tile per CTA
#define SXS  132           // sx row stride (floats): p = t_local+1, p in [0,129], padded to 132
#define SMEM_BYTES (CIN*SXS*4 + 3*CIN*NT*4 + NT*2*8)

// scratch (device globals: no allocation allowed)
__device__ float  g_y[TT_*BB*HCH];      // conv+bias output, (T,B,H), 64MB
__device__ float  g_wt[3*CIN*HCH];      // transposed weights [kk][c][h]
__device__ double g_sum[HCH];
__device__ double g_sumsq[HCH];
__device__ float  g_mean[HCH];
__device__ float  g_rs[HCH];

typedef unsigned long long ull;

__device__ __forceinline__ void fma2(ull &d, ull a, ull b){
    asm("fma.rn.f32x2 %0, %1, %2, %0;" : "+l"(d) : "l"(a), "l"(b));
}
__device__ __forceinline__ ull pack2(float x){
    ull r; asm("mov.b64 %0, {%1,%1};" : "=l"(r) : "f"(x)); return r;
}
__device__ __forceinline__ float2 unpack2(ull v){
    float2 r; asm("mov.b64 {%0,%1}, %2;" : "=f"(r.x), "=f"(r.y) : "l"(v)); return r;
}

// ---------------- prep: transpose weights, zero BN accumulators ----------------
__global__ void prep_kernel(const float* __restrict__ w){
    int i = blockIdx.x*256 + threadIdx.x;
    if (i < 3*CIN*HCH){
        int h  = i & 255;
        int ck = i >> 8;            // kk*CIN + c
        int c  = ck % CIN;
        int kk = ck / CIN;
        g_wt[i] = w[h*(CIN*3) + c*3 + kk];
    }
    if (i < HCH){ g_sum[i] = 0.0; g_sumsq[i] = 0.0; }
}

// ---------------- conv1d k=3 pad=1 + bias, fused BN partial sums ----------------
// 3 CTAs/SM (73.5KB smem each), NT=32, each thread: 4 t x 4 h outputs
__global__ void __launch_bounds__(256, 3) conv_kernel(const float* __restrict__ x,
                                                      const float* __restrict__ bias){
    extern __shared__ float smem[];
    float*  sx   = smem;                       // [CIN][SXS], p = t_local+1
    float*  sw   = smem + CIN*SXS;             // [3][CIN][NT]
    double* sred = (double*)(smem + CIN*SXS + 3*CIN*NT);  // [2*NT]

    const int tid = threadIdx.x;
    const int t0  = blockIdx.x * MT;
    const int h0  = blockIdx.y * NT;
    const int bb  = blockIdx.z;

    // load x slice (coalesced over c), transposed to [c][p], p = t_local+1 in [0,129]
    const float* xb = x + (size_t)bb*(TT_*CIN);
    for (unsigned i = tid; i < 130u*CIN; i += 256){
        unsigned p = i / CIN;                  // 0 .. 129 -> t_local = p-1
        unsigned c = i - p*CIN;
        int gt = t0 + (int)p - 1;
        float v = (gt >= 0 && gt < TT_) ? xb[(size_t)gt*CIN + c] : 0.f;
        sx[c*SXS + p] = v;
    }
    // load weight tile
    for (int i = tid; i < 3*CIN*NT; i += 256){
        int hh = i & (NT-1);
        int ck = i >> 5;
        sw[i] = g_wt[ck*256 + h0 + hh];
    }
    if (tid < 2*NT) sred[tid] = 0.0;
    __syncthreads();

    const int hx = tid & 7;        // 8 h-groups of 4
    const int tx = tid >> 3;       // 32 t-groups of 4
    const int tbase = tx * 4;      // output t_local = tbase + t', t' in 0..3

    ull acc[4][2];
    #pragma unroll
    for (int t = 0; t < 4; ++t){ acc[t][0] = 0ull; acc[t][1] = 0ull; }

    #pragma unroll 4
    for (int c = 0; c < CIN; ++c){
        // need p = tbase + t' + kk, t' in 0..3, kk in 0..2 -> aw[0..5]
        const float4* ap = reinterpret_cast<const float4*>(sx + c*SXS + tbase);
        float4 A0 = ap[0], A1 = ap[1];
        float aw[8] = {A0.x,A0.y,A0.z,A0.w, A1.x,A1.y,A1.z,A1.w};
        ull bw[3][2];
        #pragma unroll
        for (int kk = 0; kk < 3; ++kk){
            const ull* bp = reinterpret_cast<const ull*>(sw + (kk*CIN + c)*NT + hx*4);
            bw[kk][0] = bp[0]; bw[kk][1] = bp[1];
        }
        #pragma unroll
        for (int kk = 0; kk < 3; ++kk){
            #pragma unroll
            for (int t = 0; t < 4; ++t){
                ull a2 = pack2(aw[t + kk]);
                fma2(acc[t][0], a2, bw[kk][0]);
                fma2(acc[t][1], a2, bw[kk][1]);
            }
        }
    }

    float b4[4];
    #pragma unroll
    for (int j = 0; j < 4; ++j) b4[j] = bias[h0 + hx*4 + j];

    float s0=0,s1=0,s2=0,s3=0, q0=0,q1=0,q2=0,q3=0;
    float* yout = g_y + (size_t)(t0 + tbase)*(BB*HCH) + bb*HCH + h0 + hx*4;
    #pragma unroll
    for (int t = 0; t < 4; ++t){
        float2 u0 = unpack2(acc[t][0]);
        float2 u1 = unpack2(acc[t][1]);
        float y0 = u0.x + b4[0], y1 = u0.y + b4[1];
        float y2 = u1.x + b4[2], y3 = u1.y + b4[3];
        float4 o = make_float4(y0, y1, y2, y3);
        *reinterpret_cast<float4*>(yout + (size_t)t*(BB*HCH)) = o;
        s0 += y0; s1 += y1; s2 += y2; s3 += y3;
        q0 += y0*y0; q1 += y1*y1; q2 += y2*y2; q3 += y3*y3;
    }
    atomicAdd(&sred[hx*4+0], (double)s0);
    atomicAdd(&sred[hx*4+1], (double)s1);
    atomicAdd(&sred[hx*4+2], (double)s2);
    atomicAdd(&sred[hx*4+3], (double)s3);
    atomicAdd(&sred[NT + hx*4+0], (double)q0);
    atomicAdd(&sred[NT + hx*4+1], (double)q1);
    atomicAdd(&sred[NT + hx*4+2], (double)q2);
    atomicAdd(&sred[NT + hx*4+3], (double)q3);
    __syncthreads();
    if (tid < NT){
        atomicAdd(&g_sum[h0 + tid],   sred[tid]);
        atomicAdd(&g_sumsq[h0 + tid], sred[NT + tid]);
    }
}

// ---------------- BN finalize ----------------
__global__ void finalize_kernel(){
    int h = threadIdx.x;
    const double n = (double)(TT_*BB);
    double mu  = g_sum[h] / n;
    double var = g_sumsq[h] / n - mu*mu;
    g_mean[h] = (float)mu;
    g_rs[h]   = (float)(1.0 / sqrt(var + 1e-5));
}

// ---------------- LIF recurrence, T chunked with warm-up replay ----------------
// hard reset to 0 wipes history; 96-step warm-up makes chunk starts exact w.p. ~1
#define CHUNK 128
#define WARM  96
#define NCHUNK (TT_/CHUNK)
__global__ void __launch_bounds__(256) lif_kernel(const float* __restrict__ gamma,
                                                  const float* __restrict__ beta,
                                                  float* __restrict__ out){
    int g    = blockIdx.x*256 + threadIdx.x;     // 0 .. 16*8192-1
    int lane = g & (BB*HCH - 1);
    int chunk = g >> 13;
    int h = lane & 255;

    float mu = g_mean[h], rs = g_rs[h], ga = gamma[h], be = beta[h];
    int tstart = chunk * CHUNK;
    int tw = (chunk == 0) ? 0 : tstart - WARM;

    const float* yp = g_y + lane;
    float* op = out + lane;
    float v = 0.f;

    // warm-up (no stores)
    for (int t0v = tw; t0v < tstart; t0v += 8){
        float yv[8];
        #pragma unroll
        for (int j = 0; j < 8; ++j) yv[j] = yp[(size_t)(t0v + j)*(BB*HCH)];
        #pragma unroll
        for (int j = 0; j < 8; ++j){
            float yn = fmaf((yv[j] - mu)*rs, ga, be);
            v = fmaf(v, 0.5f, yn);
            bool sp = (v >= 1.0f);
            v = sp ? 0.0f : v;
        }
    }
    // main chunk
    for (int t0v = tstart; t0v < tstart + CHUNK; t0v += 8){
        float yv[8];
        #pragma unroll
        for (int j = 0; j < 8; ++j) yv[j] = yp[(size_t)(t0v + j)*(BB*HCH)];
        #pragma unroll
        for (int j = 0; j < 8; ++j){
            float yn = fmaf((yv[j] - mu)*rs, ga, be);
            v = fmaf(v, 0.5f, yn);
            bool sp = (v >= 1.0f);
            op[(size_t)(t0v + j)*(BB*HCH)] = sp ? 1.0f : 0.0f;
            v = sp ? 0.0f : v;
        }
    }
}

extern "C" void kernel_launch(void* const* d_in, const int* in_sizes, int n_in,
                              void* d_out, int out_size){
    const float* x     = (const float*)d_in[0];
    const float* w     = (const float*)d_in[1];
    const float* bias  = (const float*)d_in[2];
    const float* gamma = (const float*)d_in[3];
    const float* beta  = (const float*)d_in[4];
    float* out = (float*)d_out;

    cudaFuncSetAttribute(conv_kernel, cudaFuncAttributeMaxDynamicSharedMemorySize, SMEM_BYTES);

    prep_kernel<<<(3*CIN*HCH + 255)/256, 256>>>(w);
    conv_kernel<<<dim3(TT_/MT, HCH/NT, BB), 256, SMEM_BYTES>>>(x, bias);
    finalize_kernel<<<1, HCH>>>();
    lif_kernel<<<(BB*HCH*NCHUNK)/256, 256>>>(gamma, beta, out);
}

// round 3
// speedup vs baseline: 1.3307x; 1.3307x over previous
#include <cuda_runtime.h>
#include <math.h>

#define BB   32
#define TT_  2048
#define CIN  80
#define HCH  256
#define MT   128           // t-tile per CTA
#define NT   64            // h-tile per CTA
#define SXS  136           // sx row stride (floats), covers t_local -4..131
#define SMEM_BYTES (CIN*SXS*4 + 3*CIN*NT*4 + NT*2*8)

// scratch (device globals: no allocation allowed)
__device__ float  g_y[TT_*BB*HCH];      // conv+bias output, (T,B,H), 64MB
__device__ float  g_wt[3*CIN*HCH];      // transposed weights [kk][c][h]
__device__ double g_sum[HCH];
__device__ double g_sumsq[HCH];
__device__ float  g_mean[HCH];
__device__ float  g_rs[HCH];

typedef unsigned long long ull;

__device__ __forceinline__ void fma2(ull &d, ull a, ull b){
    asm("fma.rn.f32x2 %0, %1, %2, %0;" : "+l"(d) : "l"(a), "l"(b));
}
__device__ __forceinline__ ull pack2(float x){
    ull r; asm("mov.b64 %0, {%1,%1};" : "=l"(r) : "f"(x)); return r;
}
__device__ __forceinline__ float2 unpack2(ull v){
    float2 r; asm("mov.b64 {%0,%1}, %2;" : "=f"(r.x), "=f"(r.y) : "l"(v)); return r;
}

// ---------------- prep: transpose weights, zero BN accumulators ----------------
__global__ void prep_kernel(const float* __restrict__ w){
    int i = blockIdx.x*256 + threadIdx.x;
    if (i < 3*CIN*HCH){
        int h  = i & 255;
        int ck = i >> 8;            // kk*CIN + c
        int c  = ck % CIN;
        int kk = ck / CIN;
        g_wt[i] = w[h*(CIN*3) + c*3 + kk];
    }
    if (i < HCH){ g_sum[i] = 0.0; g_sumsq[i] = 0.0; }
}

// ---------------- conv1d k=3 pad=1 + bias, fused BN partial sums ----------------
// (R1 configuration: NT=64, 2 CTAs/SM — measured ~205us, rel_err-stable)
__global__ void __launch_bounds__(256, 2) conv_kernel(const float* __restrict__ x,
                                                      const float* __restrict__ bias){
    extern __shared__ float smem[];
    float*  sx   = smem;                       // [CIN][SXS], t_local -4..131 at +4
    float*  sw   = smem + CIN*SXS;             // [3][CIN][NT]
    double* sred = (double*)(smem + CIN*SXS + 3*CIN*NT);  // [2*NT]

    const int tid = threadIdx.x;
    const int t0  = blockIdx.x * MT;
    const int h0  = blockIdx.y * NT;
    const int bb  = blockIdx.z;

    // load x slice (coalesced over c), transposed to [c][t]
    const float* xb = x + (size_t)bb*(TT_*CIN);
    for (int i = tid; i < 130*CIN; i += 256){
        int tl = i / CIN - 1;                  // -1 .. 128
        int c  = i - (tl+1)*CIN;
        int gt = t0 + tl;
        float v = (gt >= 0 && gt < TT_) ? xb[(size_t)gt*CIN + c] : 0.f;
        sx[c*SXS + tl + 4] = v;
    }
    // load weight tile (coalesced)
    for (int i = tid; i < 3*CIN*NT; i += 256){
        int hh = i & (NT-1);
        int ck = i >> 6;
        sw[i] = g_wt[ck*256 + h0 + hh];
    }
    if (tid < 2*NT) sred[tid] = 0.0;
    __syncthreads();

    const int hx = tid & 15;
    const int tx = tid >> 4;
    const int tbase = tx * 8;

    ull acc[8][2];
    #pragma unroll
    for (int t = 0; t < 8; ++t){ acc[t][0] = 0ull; acc[t][1] = 0ull; }

    #pragma unroll 2
    for (int c = 0; c < CIN; ++c){
        const float4* ap = reinterpret_cast<const float4*>(sx + c*SXS + tbase);
        float4 A0 = ap[0], A1 = ap[1], A2 = ap[2], A3 = ap[3];
        float aw[16] = {A0.x,A0.y,A0.z,A0.w, A1.x,A1.y,A1.z,A1.w,
                        A2.x,A2.y,A2.z,A2.w, A3.x,A3.y,A3.z,A3.w};
        ull bw[3][2];
        #pragma unroll
        for (int kk = 0; kk < 3; ++kk){
            const ull* bp = reinterpret_cast<const ull*>(sw + (kk*CIN + c)*NT + hx*4);
            bw[kk][0] = bp[0]; bw[kk][1] = bp[1];
        }
        #pragma unroll
        for (int kk = 0; kk < 3; ++kk){
            #pragma unroll
            for (int t = 0; t < 8; ++t){
                ull a2 = pack2(aw[t + kk + 3]);   // t_local = tbase+t+kk-1
                fma2(acc[t][0], a2, bw[kk][0]);
                fma2(acc[t][1], a2, bw[kk][1]);
            }
        }
    }

    float b4[4];
    #pragma unroll
    for (int j = 0; j < 4; ++j) b4[j] = bias[h0 + hx*4 + j];

    float s0=0,s1=0,s2=0,s3=0, q0=0,q1=0,q2=0,q3=0;
    float* yout = g_y + (size_t)(t0 + tbase)*(BB*HCH) + bb*HCH + h0 + hx*4;
    #pragma unroll
    for (int t = 0; t < 8; ++t){
        float2 u0 = unpack2(acc[t][0]);
        float2 u1 = unpack2(acc[t][1]);
        float y0 = u0.x + b4[0], y1 = u0.y + b4[1];
        float y2 = u1.x + b4[2], y3 = u1.y + b4[3];
        float4 o = make_float4(y0, y1, y2, y3);
        *reinterpret_cast<float4*>(yout + (size_t)t*(BB*HCH)) = o;
        s0 += y0; s1 += y1; s2 += y2; s3 += y3;
        q0 += y0*y0; q1 += y1*y1; q2 += y2*y2; q3 += y3*y3;
    }
    atomicAdd(&sred[hx*4+0], (double)s0);
    atomicAdd(&sred[hx*4+1], (double)s1);
    atomicAdd(&sred[hx*4+2], (double)s2);
    atomicAdd(&sred[hx*4+3], (double)s3);
    atomicAdd(&sred[NT + hx*4+0], (double)q0);
    atomicAdd(&sred[NT + hx*4+1], (double)q1);
    atomicAdd(&sred[NT + hx*4+2], (double)q2);
    atomicAdd(&sred[NT + hx*4+3], (double)q3);
    __syncthreads();
    if (tid < NT){
        atomicAdd(&g_sum[h0 + tid],   sred[tid]);
        atomicAdd(&g_sumsq[h0 + tid], sred[NT + tid]);
    }
}

// ---------------- BN finalize ----------------
__global__ void finalize_kernel(){
    int h = threadIdx.x;
    const double n = (double)(TT_*BB);
    double mu  = g_sum[h] / n;
    double var = g_sumsq[h] / n - mu*mu;
    g_mean[h] = (float)mu;
    g_rs[h]   = (float)(1.0 / sqrt(var + 1e-5));
}

// ---------------- LIF recurrence, T chunked with warm-up replay ----------------
// hard reset to 0 wipes history; 96-step warm-up makes chunk starts exact w.p. ~1
// software-pipelined: prefetch next 8-batch while processing current (MLP 16)
#define CHUNK 128
#define WARM  96
#define NCHUNK (TT_/CHUNK)
__global__ void __launch_bounds__(256) lif_kernel(const float* __restrict__ gamma,
                                                  const float* __restrict__ beta,
                                                  float* __restrict__ out){
    int g    = blockIdx.x*256 + threadIdx.x;     // 0 .. 16*8192-1
    int lane = g & (BB*HCH - 1);
    int chunk = g >> 13;
    int h = lane & 255;

    float mu = g_mean[h], rs = g_rs[h], ga = gamma[h], be = beta[h];
    int tstart = chunk * CHUNK;
    int tw = (chunk == 0) ? 0 : tstart - WARM;
    int tend = tstart + CHUNK;

    const float* yp = g_y + lane;
    float* op = out + lane;
    float v = 0.f;

    float cur[8], nxt[8];
    #pragma unroll
    for (int j = 0; j < 8; ++j) cur[j] = yp[(size_t)(tw + j)*(BB*HCH)];

    for (int t0v = tw; t0v < tend; t0v += 8){
        int tn = t0v + 8;
        if (tn < tend){
            #pragma unroll
            for (int j = 0; j < 8; ++j) nxt[j] = yp[(size_t)(tn + j)*(BB*HCH)];
        }
        bool do_store = (t0v >= tstart);
        #pragma unroll
        for (int j = 0; j < 8; ++j){
            float yn = fmaf((cur[j] - mu)*rs, ga, be);
            v = fmaf(v, 0.5f, yn);
            bool sp = (v >= 1.0f);
            if (do_store) op[(size_t)(t0v + j)*(BB*HCH)] = sp ? 1.0f : 0.0f;
            v = sp ? 0.0f : v;
        }
        #pragma unroll
        for (int j = 0; j < 8; ++j) cur[j] = nxt[j];
    }
}

extern "C" void kernel_launch(void* const* d_in, const int* in_sizes, int n_in,
                              void* d_out, int out_size){
    const float* x     = (const float*)d_in[0];
    const float* w     = (const float*)d_in[1];
    const float* bias  = (const float*)d_in[2];
    const float* gamma = (const float*)d_in[3];
    const float* beta  = (const float*)d_in[4];
    float* out = (float*)d_out;

    cudaFuncSetAttribute(conv_kernel, cudaFuncAttributeMaxDynamicSharedMemorySize, SMEM_BYTES);

    prep_kernel<<<(3*CIN*HCH + 255)/256, 256>>>(w);
    conv_kernel<<<dim3(TT_/MT, HCH/NT, BB), 256, SMEM_BYTES>>>(x, bias);
    finalize_kernel<<<1, HCH>>>();
    lif_kernel<<<(BB*HCH*NCHUNK)/256, 256>>>(gamma, beta, out);
}